// round 10
// baseline (speedup 1.0000x reference)
#include <cuda_runtime.h>
#include <math.h>
#include <stdint.h>

#define NV 3
#define NS 20000
#define NTT 60000
#define NE 800000
#define DD 128
#define RR 6
#define INFEAT 2000
#define SCAN_BLKS 235   // ceil(60000/256)
#define NW 768          // RR * DD
#define KPAD 2048

// ---------------- device scratch ----------------
__device__ float g_h[(size_t)NTT * DD];             // projected+relu nodes [60000,128]
__device__ float g_xwt[(size_t)NTT * NW];           // transformed nodes [node][r*128+o]
__device__ float g_qn[RR * NTT];
__device__ float g_kn[RR * NTT];
__device__ float g_wT[NV][DD][KPAD];                // proj weights [v][n][k], tf32, K-major
__device__ float g_w6kt[NW][DD];                    // relation weights [r*128+o][k], tf32
__device__ float g_wq[RR * DD];
__device__ float g_wk[RR * DD];
__device__ float g_hout[(size_t)NTT * DD];          // conv output (post relu)
__device__ int   g_cnt[NTT];
__device__ int   g_offs[NTT + 1];
__device__ int   g_cur[NTT];
__device__ int   g_bsum[256];
__device__ int   g_csr[NE];                         // packed src | (type<<20)

// ---------------- helpers ----------------
__device__ __forceinline__ uint32_t smem_u32(const void* p) {
    uint32_t a;
    asm("{ .reg .u64 t; cvta.to.shared.u64 t, %1; cvt.u32.u64 %0, t; }" : "=r"(a) : "l"(p));
    return a;
}
__device__ __forceinline__ uint32_t tf32bits(float x) {
    uint32_t u;
    asm("cvt.rna.tf32.f32 %0, %1;" : "=r"(u) : "f"(x));
    return u;
}
__device__ __forceinline__ float tf32r(float x) {
    return __uint_as_float(tf32bits(x));
}
__device__ __forceinline__ void mma_tf32(float* c, const uint32_t* a, const uint32_t* b) {
    asm volatile(
        "mma.sync.aligned.m16n8k8.row.col.f32.tf32.tf32.f32 "
        "{%0,%1,%2,%3}, {%4,%5,%6,%7}, {%8,%9}, {%0,%1,%2,%3};\n"
        : "+f"(c[0]), "+f"(c[1]), "+f"(c[2]), "+f"(c[3])
        : "r"(a[0]), "r"(a[1]), "r"(a[2]), "r"(a[3]), "r"(b[0]), "r"(b[1]));
}
#define CP16(dst, src, ok) \
    asm volatile("cp.async.cg.shared.global [%0], [%1], 16, %2;" \
                 :: "r"(dst), "l"(src), "r"((ok) ? 16 : 0))

// ---------------- CSR build ----------------
__global__ void k_zero_cnt() {
    int i = blockIdx.x * 256 + threadIdx.x;
    if (i < NTT) g_cnt[i] = 0;
}
__global__ void k_count(const int* __restrict__ dst) {
    int e = blockIdx.x * 256 + threadIdx.x;
    if (e < NE) atomicAdd(&g_cnt[dst[e]], 1);
}
__global__ void k_scan1() {
    __shared__ int s[256];
    int i = blockIdx.x * 256 + threadIdx.x;
    s[threadIdx.x] = (i < NTT) ? g_cnt[i] : 0;
    __syncthreads();
    for (int o = 128; o > 0; o >>= 1) {
        if (threadIdx.x < o) s[threadIdx.x] += s[threadIdx.x + o];
        __syncthreads();
    }
    if (threadIdx.x == 0) g_bsum[blockIdx.x] = s[0];
}
__global__ void k_scan2() {
    __shared__ int s[256];
    int t = threadIdx.x;
    int v = (t < SCAN_BLKS) ? g_bsum[t] : 0;
    s[t] = v;
    __syncthreads();
    for (int o = 1; o < 256; o <<= 1) {
        int tmp = (t >= o) ? s[t - o] : 0;
        __syncthreads();
        s[t] += tmp;
        __syncthreads();
    }
    g_bsum[t] = s[t] - v;
}
__global__ void k_scan3() {
    __shared__ int s[256];
    int t = threadIdx.x;
    int i = blockIdx.x * 256 + t;
    int v = (i < NTT) ? g_cnt[i] : 0;
    s[t] = v;
    __syncthreads();
    for (int o = 1; o < 256; o <<= 1) {
        int tmp = (t >= o) ? s[t - o] : 0;
        __syncthreads();
        s[t] += tmp;
        __syncthreads();
    }
    int excl = s[t] - v + g_bsum[blockIdx.x];
    if (i < NTT) {
        g_offs[i] = excl;
        g_cur[i] = excl;
        if (i == NTT - 1) g_offs[NTT] = excl + v;
    }
}
__global__ void k_scatter(const int* __restrict__ src, const int* __restrict__ dst,
                          const int* __restrict__ typ) {
    int e = blockIdx.x * 256 + threadIdx.x;
    if (e >= NE) return;
    int d = dst[e];
    int pos = atomicAdd(&g_cur[d], 1);
    g_csr[pos] = src[e] | (typ[e] << 20);
}

// ---------------- weight prep ----------------
// g_wT[v][n][k] = tf32(w_proj_v[k][n]), zero-padded k in [2000,2048)
__global__ void k_wtrans(const float* __restrict__ w0, const float* __restrict__ w1,
                         const float* __restrict__ w2) {
    int idx = blockIdx.x * 256 + threadIdx.x;   // over 3*128*2048
    if (idx >= NV * DD * KPAD) return;
    int v = idx / (DD * KPAD);
    int rem = idx - v * (DD * KPAD);
    int n = rem >> 11, k = rem & (KPAD - 1);
    const float* w = (v == 0) ? w0 : (v == 1) ? w1 : w2;
    float val = (k < INFEAT) ? w[(long)k * DD + n] : 0.f;
    (&g_wT[0][0][0])[idx] = tf32r(val);
}

// g_w6kt[r*128+o][d] = tf32(sum_b comp[r][b] * basis[b][d][o])
__global__ void k_wprep(const float* __restrict__ basis, const float* __restrict__ comp) {
    int idx = blockIdx.x * 256 + threadIdx.x;   // over 768*128
    if (idx >= NW * DD) return;
    int row = idx >> 7;          // r*128+o
    int d = idx & 127;
    int r = row >> 7, o = row & 127;
    float s = 0.f;
#pragma unroll
    for (int b = 0; b < 4; b++) s += comp[r * 4 + b] * basis[b * DD * DD + d * DD + o];
    (&g_w6kt[0][0])[idx] = tf32r(s);
}

__global__ void k_wqk(const float* __restrict__ att_q, const float* __restrict__ att_k) {
    int idx = blockIdx.x * 256 + threadIdx.x;     // over 6*128 (r,d)
    if (idx >= RR * DD) return;
    int r = idx / DD, d = idx - r * DD;
    float sq = 0.f, sk = 0.f;
#pragma unroll 8
    for (int o = 0; o < DD; o++) {
        float v = g_w6kt[(r << 7) + o][d];
        sq += v * att_q[o];
        sk += v * att_k[o];
    }
    g_wq[idx] = sq;
    g_wk[idx] = sk;
}

// ---------------- per-(relation,node) attention scalars ----------------
__global__ void k_qk() {
    __shared__ float swq[RR * DD], swk[RR * DD];
    for (int i = threadIdx.x; i < RR * DD; i += 256) {
        swq[i] = g_wq[i];
        swk[i] = g_wk[i];
    }
    __syncthreads();
    int warp = threadIdx.x >> 5, lane = threadIdx.x & 31;
    int n = blockIdx.x * 8 + warp;
    if (n >= NTT) return;
    float4 hv = ((const float4*)(g_h + (size_t)n * DD))[lane];
#pragma unroll
    for (int r = 0; r < RR; r++) {
        float4 wqv = ((const float4*)(swq + r * DD))[lane];
        float4 wkv = ((const float4*)(swk + r * DD))[lane];
        float pq = hv.x * wqv.x + hv.y * wqv.y + hv.z * wqv.z + hv.w * wqv.w;
        float pk = hv.x * wkv.x + hv.y * wkv.y + hv.z * wkv.z + hv.w * wkv.w;
        for (int o = 16; o; o >>= 1) {
            pq += __shfl_xor_sync(0xFFFFFFFFu, pq, o);
            pk += __shfl_xor_sync(0xFFFFFFFFu, pk, o);
        }
        if (lane == 0) {
            g_qn[r * NTT + n] = pq;
            g_kn[r * NTT + n] = pk;
        }
    }
}

// ---------------- mma.sync tf32 GEMM v2 ----------------
// CTA 128x128, 4 warps (warp tile 64x64), BK=32, 3-stage cp.async pipeline.
// smem per stage: A[128][36] + B[128][36] floats (both [row][k], K-major sources).
#define GSTR 36
#define STAGEF (128 * GSTR * 2)            // floats per stage (A then B)
#define SMEM_GEMM (3 * STAGEF * 4)         // 110592 bytes

__device__ __forceinline__ void ld_stage(
    const float* __restrict__ A, int lda,
    const float* __restrict__ B, int ldb,
    int M, int K, int m0, int n0, int i,
    float* __restrict__ sm, int s, int t)
{
    float* As = sm + s * STAGEF;
    float* Bs = As + 128 * GSTR;
    int k0 = i << 5;
    // A: thread t loads row t (32 floats = 8x16B)
    {
        int gm = m0 + t;
        int rok = (gm < M);
        const float* src = A + (long)(rok ? gm : (M - 1)) * lda + k0;
        uint32_t dst = smem_u32(As + t * GSTR);
#pragma unroll
        for (int c = 0; c < 8; c++) {
            int ok = rok && (k0 + c * 4 < K);
            CP16(dst + c * 16, src + c * 4, ok);
        }
    }
    // B: thread t loads n-row n0+t (K-major global)
    {
        const float* src = B + (long)(n0 + t) * ldb + k0;
        uint32_t dst = smem_u32(Bs + t * GSTR);
#pragma unroll
        for (int c = 0; c < 8; c++) {
            int ok = (k0 + c * 4 < K);
            CP16(dst + c * 16, src + c * 4, ok);
        }
    }
    asm volatile("cp.async.commit_group;" ::: "memory");
}

__device__ __forceinline__ void gemm_tc(
    const float* __restrict__ A, int lda,
    const float* __restrict__ B, int ldb,
    const float* __restrict__ bias,
    float* __restrict__ C, int ldc,
    int M, int K, int m0, int n0, int relu)
{
    extern __shared__ float sm[];
    int t = threadIdx.x, wid = t >> 5, lane = t & 31;
    int wm = (wid & 1) * 64, wn = (wid >> 1) * 64;
    int tr = lane >> 2, tc = lane & 3;

    float acc[4][8][4];
#pragma unroll
    for (int mt = 0; mt < 4; mt++)
#pragma unroll
        for (int nt = 0; nt < 8; nt++)
#pragma unroll
            for (int i = 0; i < 4; i++) acc[mt][nt][i] = 0.f;

    int nc = (K + 31) >> 5;
    int pre = nc < 3 ? nc : 3;
    for (int i = 0; i < pre; i++) ld_stage(A, lda, B, ldb, M, K, m0, n0, i, sm, i, t);

    for (int i = 0; i < nc; i++) {
        int rem = nc - 1 - i;
        if (rem >= 2)      asm volatile("cp.async.wait_group 2;" ::: "memory");
        else if (rem == 1) asm volatile("cp.async.wait_group 1;" ::: "memory");
        else               asm volatile("cp.async.wait_group 0;" ::: "memory");
        __syncthreads();

        int s = i - (i / 3) * 3;
        const float* As = sm + s * STAGEF;
        const float* Bs = As + 128 * GSTR;

#pragma unroll
        for (int kb = 0; kb < 32; kb += 8) {
            uint32_t a[4][4], b[8][2];
#pragma unroll
            for (int mt = 0; mt < 4; mt++) {
                int r0 = wm + mt * 16 + tr;
                a[mt][0] = tf32bits(As[r0 * GSTR + kb + tc]);
                a[mt][1] = tf32bits(As[(r0 + 8) * GSTR + kb + tc]);
                a[mt][2] = tf32bits(As[r0 * GSTR + kb + tc + 4]);
                a[mt][3] = tf32bits(As[(r0 + 8) * GSTR + kb + tc + 4]);
            }
#pragma unroll
            for (int nt = 0; nt < 8; nt++) {
                int n = wn + nt * 8 + tr;
                b[nt][0] = __float_as_uint(Bs[n * GSTR + kb + tc]);
                b[nt][1] = __float_as_uint(Bs[n * GSTR + kb + tc + 4]);
            }
#pragma unroll
            for (int mt = 0; mt < 4; mt++)
#pragma unroll
                for (int nt = 0; nt < 8; nt++)
                    mma_tf32(acc[mt][nt], a[mt], b[nt]);
        }

        if (i + 3 < nc) {
            __syncthreads();
            ld_stage(A, lda, B, ldb, M, K, m0, n0, i + 3, sm, s, t);
        }
    }

    // epilogue
#pragma unroll
    for (int mt = 0; mt < 4; mt++) {
#pragma unroll
        for (int half = 0; half < 2; half++) {
            int grow = m0 + wm + mt * 16 + tr + half * 8;
            if (grow >= M) continue;
#pragma unroll
            for (int nt = 0; nt < 8; nt++) {
                int col = wn + nt * 8 + tc * 2;
                float v0 = acc[mt][nt][half * 2 + 0];
                float v1 = acc[mt][nt][half * 2 + 1];
                if (bias) { v0 += bias[col]; v1 += bias[col + 1]; }
                if (relu) { v0 = fmaxf(v0, 0.f); v1 = fmaxf(v1, 0.f); }
                *(float2*)(C + (long)grow * ldc + n0 + col) = make_float2(v0, v1);
            }
        }
    }
}

__global__ __launch_bounds__(128) void k_proj_mma2(
    const float* __restrict__ x0, const float* __restrict__ x1, const float* __restrict__ x2,
    const float* __restrict__ b0, const float* __restrict__ b1, const float* __restrict__ b2)
{
    int v = blockIdx.y;
    const float* A = (v == 0) ? x0 : (v == 1) ? x1 : x2;
    const float* bi = (v == 0) ? b0 : (v == 1) ? b1 : b2;
    gemm_tc(A, INFEAT, &g_wT[v][0][0], KPAD, bi,
            g_h + (long)v * NS * DD, DD,
            NS, INFEAT, blockIdx.x * 128, 0, 1);
}

__global__ __launch_bounds__(128) void k_xw_mma2() {
    gemm_tc(g_h, DD, &g_w6kt[0][0], DD, nullptr,
            g_xwt, NW,
            NTT, DD, blockIdx.x * 128, blockIdx.y * 128, 0);
}

// ---------------- warp-per-dst softmax + aggregation ----------------
__global__ void k_aggregate(const float* __restrict__ conv_bias) {
    int warp = threadIdx.x >> 5, lane = threadIdx.x & 31;
    int d = blockIdx.x * 8 + warp;
    if (d >= NTT) return;
    int s = g_offs[d], e1 = g_offs[d + 1];

    float m = -INFINITY;
    for (int i = s + lane; i < e1; i += 32) {
        int p = g_csr[i];
        int src = p & 0xFFFFF;
        int t = p >> 20;
        float a = g_qn[t * NTT + d] + g_kn[t * NTT + src];
        a = a > 0.f ? a : 0.2f * a;
        m = fmaxf(m, a);
    }
    for (int o = 16; o; o >>= 1) m = fmaxf(m, __shfl_xor_sync(0xFFFFFFFFu, m, o));

    float4 acc = make_float4(0.f, 0.f, 0.f, 0.f);
    float den = 0.f;
    for (int i = s; i < e1; i++) {
        int p = g_csr[i];
        int src = p & 0xFFFFF;
        int t = p >> 20;
        float a = g_qn[t * NTT + d] + g_kn[t * NTT + src];
        a = a > 0.f ? a : 0.2f * a;
        float w = __expf(a - m);
        den += w;
        float4 v = ((const float4*)(g_xwt + (size_t)src * NW + t * DD))[lane];
        acc.x += w * v.x;
        acc.y += w * v.y;
        acc.z += w * v.z;
        acc.w += w * v.w;
    }
    float inv = 1.f / (den + 1e-16f);
    float4 b = ((const float4*)conv_bias)[lane];
    float4 o;
    o.x = fmaxf(acc.x * inv + b.x, 0.f);
    o.y = fmaxf(acc.y * inv + b.y, 0.f);
    o.z = fmaxf(acc.z * inv + b.z, 0.f);
    o.w = fmaxf(acc.w * inv + b.w, 0.f);
    ((float4*)(g_hout + (size_t)d * DD))[lane] = o;
}

// ---------------- final linear: [20000,384] @ [384,5] + bias ----------------
__global__ void k_final(const float* __restrict__ w_int, const float* __restrict__ b_int,
                        float* __restrict__ out) {
    int warp = threadIdx.x >> 5, lane = threadIdx.x & 31;
    int n = blockIdx.x * 8 + warp;
    if (n >= NS) return;
    float a0 = 0.f, a1 = 0.f, a2 = 0.f, a3 = 0.f, a4 = 0.f;
    for (int k = lane; k < NV * DD; k += 32) {
        int v = k >> 7, dd = k & 127;
        float f = g_hout[((size_t)(v * NS + n)) * DD + dd];
        const float* wr = w_int + (size_t)k * 5;
        a0 += f * wr[0];
        a1 += f * wr[1];
        a2 += f * wr[2];
        a3 += f * wr[3];
        a4 += f * wr[4];
    }
    for (int o = 16; o; o >>= 1) {
        a0 += __shfl_xor_sync(0xFFFFFFFFu, a0, o);
        a1 += __shfl_xor_sync(0xFFFFFFFFu, a1, o);
        a2 += __shfl_xor_sync(0xFFFFFFFFu, a2, o);
        a3 += __shfl_xor_sync(0xFFFFFFFFu, a3, o);
        a4 += __shfl_xor_sync(0xFFFFFFFFu, a4, o);
    }
    if (lane == 0) {
        float* op = out + (size_t)n * 5;
        op[0] = a0 + b_int[0];
        op[1] = a1 + b_int[1];
        op[2] = a2 + b_int[2];
        op[3] = a3 + b_int[3];
        op[4] = a4 + b_int[4];
    }
}

// ---------------- launch ----------------
extern "C" void kernel_launch(void* const* d_in, const int* in_sizes, int n_in,
                              void* d_out, int out_size) {
    const float* x0   = (const float*)d_in[0];
    const float* wp0  = (const float*)d_in[1];
    const float* bp0  = (const float*)d_in[2];
    const float* x1   = (const float*)d_in[3];
    const float* wp1  = (const float*)d_in[4];
    const float* bp1  = (const float*)d_in[5];
    const float* x2   = (const float*)d_in[6];
    const float* wp2  = (const float*)d_in[7];
    const float* bp2  = (const float*)d_in[8];
    const int*   esrc = (const int*)d_in[9];
    const int*   edst = (const int*)d_in[10];
    const int*   etyp = (const int*)d_in[11];
    const float* basis = (const float*)d_in[12];
    const float* comp  = (const float*)d_in[13];
    const float* attq  = (const float*)d_in[14];
    const float* attk  = (const float*)d_in[15];
    const float* cbias = (const float*)d_in[16];
    const float* wint  = (const float*)d_in[17];
    const float* bint  = (const float*)d_in[18];
    float* out = (float*)d_out;

    static int smem_set = 0;
    if (!smem_set) {
        cudaFuncSetAttribute(k_proj_mma2, cudaFuncAttributeMaxDynamicSharedMemorySize, SMEM_GEMM);
        cudaFuncSetAttribute(k_xw_mma2, cudaFuncAttributeMaxDynamicSharedMemorySize, SMEM_GEMM);
        smem_set = 1;
    }

    // CSR build
    k_zero_cnt<<<SCAN_BLKS, 256>>>();
    k_count<<<NE / 256, 256>>>(edst);
    k_scan1<<<SCAN_BLKS, 256>>>();
    k_scan2<<<1, 256>>>();
    k_scan3<<<SCAN_BLKS, 256>>>();
    k_scatter<<<NE / 256, 256>>>(esrc, edst, etyp);

    // weight prep (tf32 pre-rounded, K-major)
    k_wtrans<<<(NV * DD * KPAD) / 256, 256>>>(wp0, wp1, wp2);
    k_wprep<<<(NW * DD + 255) / 256, 256>>>(basis, comp);
    k_wqk<<<(RR * DD + 255) / 256, 256>>>(attq, attk);

    // projections: grid (157 m-tiles, 3 views)
    dim3 gp((NS + 127) / 128, NV);
    k_proj_mma2<<<gp, 128, SMEM_GEMM>>>(x0, x1, x2, bp0, bp1, bp2);

    // xwt = h @ w6 : grid (469 m-tiles, 6 relations)
    dim3 gx((NTT + 127) / 128, RR);
    k_xw_mma2<<<gx, 128, SMEM_GEMM>>>();

    // attention scalars per (relation, node)
    k_qk<<<NTT / 8, 256>>>();

    // softmax + aggregation + relu
    k_aggregate<<<NTT / 8, 256>>>(cbias);

    // final classification head
    k_final<<<NS / 8, 256>>>(wint, bint, out);
}

// round 11
// speedup vs baseline: 1.3880x; 1.3880x over previous
#include <cuda_runtime.h>
#include <math.h>
#include <stdint.h>

#define NV 3
#define NS 20000
#define NTT 60000
#define NE 800000
#define DD 128
#define RR 6
#define INFEAT 2000
#define SCAN_BLKS 235   // ceil(60000/256)
#define NW 768          // RR * DD
#define KPAD 2048

// ---------------- device scratch ----------------
__device__ float g_h[(size_t)NTT * DD];             // projected+relu nodes [60000,128]
__device__ float g_xwt[(size_t)NTT * NW];           // transformed nodes [node][r*128+o]
__device__ float g_qn[RR * NTT];
__device__ float g_kn[RR * NTT];
__device__ float g_wT[NV][DD][KPAD];                // proj weights [v][n][k], tf32, K-major
__device__ float g_w6kt[NW][DD];                    // relation weights [r*128+o][k], tf32
__device__ float g_wq[RR * DD];
__device__ float g_wk[RR * DD];
__device__ float g_hout[(size_t)NTT * DD];          // conv output (post relu)
__device__ int   g_cnt[NTT];
__device__ int   g_offs[NTT + 1];
__device__ int   g_cur[NTT];
__device__ int   g_bsum[256];
__device__ int   g_csr[NE];                         // packed src | (type<<20)

// ---------------- helpers ----------------
__device__ __forceinline__ uint32_t smem_u32(const void* p) {
    uint32_t a;
    asm("{ .reg .u64 t; cvta.to.shared.u64 t, %1; cvt.u32.u64 %0, t; }" : "=r"(a) : "l"(p));
    return a;
}
__device__ __forceinline__ uint32_t tf32bits(float x) {
    uint32_t u;
    asm("cvt.rna.tf32.f32 %0, %1;" : "=r"(u) : "f"(x));
    return u;
}
__device__ __forceinline__ float tf32r(float x) {
    return __uint_as_float(tf32bits(x));
}
__device__ __forceinline__ void mma_tf32(float* c, const uint32_t* a, const uint32_t* b) {
    asm volatile(
        "mma.sync.aligned.m16n8k8.row.col.f32.tf32.tf32.f32 "
        "{%0,%1,%2,%3}, {%4,%5,%6,%7}, {%8,%9}, {%0,%1,%2,%3};\n"
        : "+f"(c[0]), "+f"(c[1]), "+f"(c[2]), "+f"(c[3])
        : "r"(a[0]), "r"(a[1]), "r"(a[2]), "r"(a[3]), "r"(b[0]), "r"(b[1]));
}
#define CP16(dst, src, ok) \
    asm volatile("cp.async.cg.shared.global [%0], [%1], 16, %2;" \
                 :: "r"(dst), "l"(src), "r"((ok) ? 16 : 0))

// ---------------- CSR build ----------------
__global__ void k_zero_cnt() {
    int i = blockIdx.x * 256 + threadIdx.x;
    if (i < NTT) g_cnt[i] = 0;
}
__global__ void k_count(const int* __restrict__ dst) {
    int e = blockIdx.x * 256 + threadIdx.x;
    if (e < NE) atomicAdd(&g_cnt[dst[e]], 1);
}
__global__ void k_scan1() {
    __shared__ int s[256];
    int i = blockIdx.x * 256 + threadIdx.x;
    s[threadIdx.x] = (i < NTT) ? g_cnt[i] : 0;
    __syncthreads();
    for (int o = 128; o > 0; o >>= 1) {
        if (threadIdx.x < o) s[threadIdx.x] += s[threadIdx.x + o];
        __syncthreads();
    }
    if (threadIdx.x == 0) g_bsum[blockIdx.x] = s[0];
}
__global__ void k_scan2() {
    __shared__ int s[256];
    int t = threadIdx.x;
    int v = (t < SCAN_BLKS) ? g_bsum[t] : 0;
    s[t] = v;
    __syncthreads();
    for (int o = 1; o < 256; o <<= 1) {
        int tmp = (t >= o) ? s[t - o] : 0;
        __syncthreads();
        s[t] += tmp;
        __syncthreads();
    }
    g_bsum[t] = s[t] - v;
}
__global__ void k_scan3() {
    __shared__ int s[256];
    int t = threadIdx.x;
    int i = blockIdx.x * 256 + t;
    int v = (i < NTT) ? g_cnt[i] : 0;
    s[t] = v;
    __syncthreads();
    for (int o = 1; o < 256; o <<= 1) {
        int tmp = (t >= o) ? s[t - o] : 0;
        __syncthreads();
        s[t] += tmp;
        __syncthreads();
    }
    int excl = s[t] - v + g_bsum[blockIdx.x];
    if (i < NTT) {
        g_offs[i] = excl;
        g_cur[i] = excl;
        if (i == NTT - 1) g_offs[NTT] = excl + v;
    }
}
__global__ void k_scatter(const int* __restrict__ src, const int* __restrict__ dst,
                          const int* __restrict__ typ) {
    int e = blockIdx.x * 256 + threadIdx.x;
    if (e >= NE) return;
    int d = dst[e];
    int pos = atomicAdd(&g_cur[d], 1);
    g_csr[pos] = src[e] | (typ[e] << 20);
}

// ---------------- weight prep ----------------
__global__ void k_wtrans(const float* __restrict__ w0, const float* __restrict__ w1,
                         const float* __restrict__ w2) {
    int idx = blockIdx.x * 256 + threadIdx.x;   // over 3*128*2048
    if (idx >= NV * DD * KPAD) return;
    int v = idx / (DD * KPAD);
    int rem = idx - v * (DD * KPAD);
    int n = rem >> 11, k = rem & (KPAD - 1);
    const float* w = (v == 0) ? w0 : (v == 1) ? w1 : w2;
    float val = (k < INFEAT) ? w[(long)k * DD + n] : 0.f;
    (&g_wT[0][0][0])[idx] = tf32r(val);
}

__global__ void k_wprep(const float* __restrict__ basis, const float* __restrict__ comp) {
    int idx = blockIdx.x * 256 + threadIdx.x;   // over 768*128
    if (idx >= NW * DD) return;
    int row = idx >> 7;          // r*128+o
    int d = idx & 127;
    int r = row >> 7, o = row & 127;
    float s = 0.f;
#pragma unroll
    for (int b = 0; b < 4; b++) s += comp[r * 4 + b] * basis[b * DD * DD + d * DD + o];
    (&g_w6kt[0][0])[idx] = tf32r(s);
}

__global__ void k_wqk(const float* __restrict__ att_q, const float* __restrict__ att_k) {
    int idx = blockIdx.x * 256 + threadIdx.x;     // over 6*128 (r,d)
    if (idx >= RR * DD) return;
    int r = idx / DD, d = idx - r * DD;
    float sq = 0.f, sk = 0.f;
#pragma unroll 8
    for (int o = 0; o < DD; o++) {
        float v = g_w6kt[(r << 7) + o][d];
        sq += v * att_q[o];
        sk += v * att_k[o];
    }
    g_wq[idx] = sq;
    g_wk[idx] = sk;
}

// ---------------- per-(relation,node) attention scalars ----------------
__global__ void k_qk() {
    __shared__ float swq[RR * DD], swk[RR * DD];
    for (int i = threadIdx.x; i < RR * DD; i += 256) {
        swq[i] = g_wq[i];
        swk[i] = g_wk[i];
    }
    __syncthreads();
    int warp = threadIdx.x >> 5, lane = threadIdx.x & 31;
    int n = blockIdx.x * 8 + warp;
    if (n >= NTT) return;
    float4 hv = ((const float4*)(g_h + (size_t)n * DD))[lane];
#pragma unroll
    for (int r = 0; r < RR; r++) {
        float4 wqv = ((const float4*)(swq + r * DD))[lane];
        float4 wkv = ((const float4*)(swk + r * DD))[lane];
        float pq = hv.x * wqv.x + hv.y * wqv.y + hv.z * wqv.z + hv.w * wqv.w;
        float pk = hv.x * wkv.x + hv.y * wkv.y + hv.z * wkv.z + hv.w * wkv.w;
        for (int o = 16; o; o >>= 1) {
            pq += __shfl_xor_sync(0xFFFFFFFFu, pq, o);
            pk += __shfl_xor_sync(0xFFFFFFFFu, pk, o);
        }
        if (lane == 0) {
            g_qn[r * NTT + n] = pq;
            g_kn[r * NTT + n] = pk;
        }
    }
}

// ---------------- mma.sync tf32 GEMM v3 ----------------
// CTA 128x128, 8 warps (warp grid 2Mx4N, warp tile 64x32), BK=32, 3-stage cp.async.
// smem per stage: A[128][36] + B[128][36] floats ([row][k], both sources K-major).
#define GSTR 36
#define STAGEF (128 * GSTR * 2)            // floats per stage (A then B)
#define SMEM_GEMM (3 * STAGEF * 4)         // 110592 bytes

__device__ __forceinline__ void ld_stage(
    const float* __restrict__ A, int lda,
    const float* __restrict__ B, int ldb,
    int M, int K, int m0, int n0, int i,
    float* __restrict__ sm, int s, int t)
{
    float* As = sm + s * STAGEF;
    float* Bs = As + 128 * GSTR;
    int k0 = i << 5;
    // A: 1024 16B-chunks; 8 consecutive lanes cover 128B contiguous of one row
#pragma unroll
    for (int j = 0; j < 4; j++) {
        int idx = t + (j << 8);
        int row = idx >> 3, kc = (idx & 7) * 4;
        int gm = m0 + row;
        int rok = (gm < M);
        const float* src = A + (long)(rok ? gm : (M - 1)) * lda + k0 + kc;
        int ok = rok && (k0 + kc < K);
        CP16(smem_u32(As + row * GSTR + kc), src, ok);
    }
#pragma unroll
    for (int j = 0; j < 4; j++) {
        int idx = t + (j << 8);
        int row = idx >> 3, kc = (idx & 7) * 4;
        const float* src = B + (long)(n0 + row) * ldb + k0 + kc;
        int ok = (k0 + kc < K);
        CP16(smem_u32(Bs + row * GSTR + kc), src, ok);
    }
    asm volatile("cp.async.commit_group;" ::: "memory");
}

__device__ __forceinline__ void gemm_tc(
    const float* __restrict__ A, int lda,
    const float* __restrict__ B, int ldb,
    const float* __restrict__ bias,
    float* __restrict__ C, int ldc,
    int M, int K, int m0, int n0, int relu)
{
    extern __shared__ float sm[];
    int t = threadIdx.x, wid = t >> 5, lane = t & 31;
    int wm = (wid & 1) * 64, wn = (wid >> 1) * 32;
    int tr = lane >> 2, tc = lane & 3;

    float acc[4][4][4];
#pragma unroll
    for (int mt = 0; mt < 4; mt++)
#pragma unroll
        for (int nt = 0; nt < 4; nt++)
#pragma unroll
            for (int i = 0; i < 4; i++) acc[mt][nt][i] = 0.f;

    int nc = (K + 31) >> 5;
    int pre = nc < 3 ? nc : 3;
    for (int i = 0; i < pre; i++) ld_stage(A, lda, B, ldb, M, K, m0, n0, i, sm, i, t);

    for (int i = 0; i < nc; i++) {
        int rem = nc - 1 - i;
        if (rem >= 2)      asm volatile("cp.async.wait_group 2;" ::: "memory");
        else if (rem == 1) asm volatile("cp.async.wait_group 1;" ::: "memory");
        else               asm volatile("cp.async.wait_group 0;" ::: "memory");
        __syncthreads();

        int s = i - (i / 3) * 3;
        const float* As = sm + s * STAGEF;
        const float* Bs = As + 128 * GSTR;

#pragma unroll
        for (int kb = 0; kb < 32; kb += 8) {
            uint32_t a[4][4], b[4][2];
#pragma unroll
            for (int mt = 0; mt < 4; mt++) {
                int r0 = wm + mt * 16 + tr;
                a[mt][0] = tf32bits(As[r0 * GSTR + kb + tc]);
                a[mt][1] = tf32bits(As[(r0 + 8) * GSTR + kb + tc]);
                a[mt][2] = tf32bits(As[r0 * GSTR + kb + tc + 4]);
                a[mt][3] = tf32bits(As[(r0 + 8) * GSTR + kb + tc + 4]);
            }
#pragma unroll
            for (int nt = 0; nt < 4; nt++) {
                int n = wn + nt * 8 + tr;
                b[nt][0] = __float_as_uint(Bs[n * GSTR + kb + tc]);
                b[nt][1] = __float_as_uint(Bs[n * GSTR + kb + tc + 4]);
            }
#pragma unroll
            for (int mt = 0; mt < 4; mt++)
#pragma unroll
                for (int nt = 0; nt < 4; nt++)
                    mma_tf32(acc[mt][nt], a[mt], b[nt]);
        }

        if (i + 3 < nc) {
            __syncthreads();
            ld_stage(A, lda, B, ldb, M, K, m0, n0, i + 3, sm, s, t);
        }
    }

    // epilogue
#pragma unroll
    for (int mt = 0; mt < 4; mt++) {
#pragma unroll
        for (int half = 0; half < 2; half++) {
            int grow = m0 + wm + mt * 16 + tr + half * 8;
            if (grow >= M) continue;
#pragma unroll
            for (int nt = 0; nt < 4; nt++) {
                int col = wn + nt * 8 + tc * 2;
                float v0 = acc[mt][nt][half * 2 + 0];
                float v1 = acc[mt][nt][half * 2 + 1];
                if (bias) { v0 += bias[col]; v1 += bias[col + 1]; }
                if (relu) { v0 = fmaxf(v0, 0.f); v1 = fmaxf(v1, 0.f); }
                *(float2*)(C + (long)grow * ldc + n0 + col) = make_float2(v0, v1);
            }
        }
    }
}

__global__ __launch_bounds__(256, 2) void k_proj_mma3(
    const float* __restrict__ x0, const float* __restrict__ x1, const float* __restrict__ x2,
    const float* __restrict__ b0, const float* __restrict__ b1, const float* __restrict__ b2)
{
    int v = blockIdx.y;
    const float* A = (v == 0) ? x0 : (v == 1) ? x1 : x2;
    const float* bi = (v == 0) ? b0 : (v == 1) ? b1 : b2;
    gemm_tc(A, INFEAT, &g_wT[v][0][0], KPAD, bi,
            g_h + (long)v * NS * DD, DD,
            NS, INFEAT, blockIdx.x * 128, 0, 1);
}

__global__ __launch_bounds__(256, 2) void k_xw_mma3() {
    gemm_tc(g_h, DD, &g_w6kt[0][0], DD, nullptr,
            g_xwt, NW,
            NTT, DD, blockIdx.x * 128, blockIdx.y * 128, 0);
}

// ---------------- warp-per-dst softmax + aggregation ----------------
__global__ void k_aggregate(const float* __restrict__ conv_bias) {
    int warp = threadIdx.x >> 5, lane = threadIdx.x & 31;
    int d = blockIdx.x * 8 + warp;
    if (d >= NTT) return;
    int s = g_offs[d], e1 = g_offs[d + 1];

    float m = -INFINITY;
    for (int i = s + lane; i < e1; i += 32) {
        int p = g_csr[i];
        int src = p & 0xFFFFF;
        int t = p >> 20;
        float a = g_qn[t * NTT + d] + g_kn[t * NTT + src];
        a = a > 0.f ? a : 0.2f * a;
        m = fmaxf(m, a);
    }
    for (int o = 16; o; o >>= 1) m = fmaxf(m, __shfl_xor_sync(0xFFFFFFFFu, m, o));

    float4 acc = make_float4(0.f, 0.f, 0.f, 0.f);
    float den = 0.f;
    for (int i = s; i < e1; i++) {
        int p = g_csr[i];
        int src = p & 0xFFFFF;
        int t = p >> 20;
        float a = g_qn[t * NTT + d] + g_kn[t * NTT + src];
        a = a > 0.f ? a : 0.2f * a;
        float w = __expf(a - m);
        den += w;
        float4 v = ((const float4*)(g_xwt + (size_t)src * NW + t * DD))[lane];
        acc.x += w * v.x;
        acc.y += w * v.y;
        acc.z += w * v.z;
        acc.w += w * v.w;
    }
    float inv = 1.f / (den + 1e-16f);
    float4 b = ((const float4*)conv_bias)[lane];
    float4 o;
    o.x = fmaxf(acc.x * inv + b.x, 0.f);
    o.y = fmaxf(acc.y * inv + b.y, 0.f);
    o.z = fmaxf(acc.z * inv + b.z, 0.f);
    o.w = fmaxf(acc.w * inv + b.w, 0.f);
    ((float4*)(g_hout + (size_t)d * DD))[lane] = o;
}

// ---------------- final linear: [20000,384] @ [384,5] + bias ----------------
__global__ void k_final(const float* __restrict__ w_int, const float* __restrict__ b_int,
                        float* __restrict__ out) {
    int warp = threadIdx.x >> 5, lane = threadIdx.x & 31;
    int n = blockIdx.x * 8 + warp;
    if (n >= NS) return;
    float a0 = 0.f, a1 = 0.f, a2 = 0.f, a3 = 0.f, a4 = 0.f;
    for (int k = lane; k < NV * DD; k += 32) {
        int v = k >> 7, dd = k & 127;
        float f = g_hout[((size_t)(v * NS + n)) * DD + dd];
        const float* wr = w_int + (size_t)k * 5;
        a0 += f * wr[0];
        a1 += f * wr[1];
        a2 += f * wr[2];
        a3 += f * wr[3];
        a4 += f * wr[4];
    }
    for (int o = 16; o; o >>= 1) {
        a0 += __shfl_xor_sync(0xFFFFFFFFu, a0, o);
        a1 += __shfl_xor_sync(0xFFFFFFFFu, a1, o);
        a2 += __shfl_xor_sync(0xFFFFFFFFu, a2, o);
        a3 += __shfl_xor_sync(0xFFFFFFFFu, a3, o);
        a4 += __shfl_xor_sync(0xFFFFFFFFu, a4, o);
    }
    if (lane == 0) {
        float* op = out + (size_t)n * 5;
        op[0] = a0 + b_int[0];
        op[1] = a1 + b_int[1];
        op[2] = a2 + b_int[2];
        op[3] = a3 + b_int[3];
        op[4] = a4 + b_int[4];
    }
}

// ---------------- launch ----------------
extern "C" void kernel_launch(void* const* d_in, const int* in_sizes, int n_in,
                              void* d_out, int out_size) {
    const float* x0   = (const float*)d_in[0];
    const float* wp0  = (const float*)d_in[1];
    const float* bp0  = (const float*)d_in[2];
    const float* x1   = (const float*)d_in[3];
    const float* wp1  = (const float*)d_in[4];
    const float* bp1  = (const float*)d_in[5];
    const float* x2   = (const float*)d_in[6];
    const float* wp2  = (const float*)d_in[7];
    const float* bp2  = (const float*)d_in[8];
    const int*   esrc = (const int*)d_in[9];
    const int*   edst = (const int*)d_in[10];
    const int*   etyp = (const int*)d_in[11];
    const float* basis = (const float*)d_in[12];
    const float* comp  = (const float*)d_in[13];
    const float* attq  = (const float*)d_in[14];
    const float* attk  = (const float*)d_in[15];
    const float* cbias = (const float*)d_in[16];
    const float* wint  = (const float*)d_in[17];
    const float* bint  = (const float*)d_in[18];
    float* out = (float*)d_out;

    static int smem_set = 0;
    if (!smem_set) {
        cudaFuncSetAttribute(k_proj_mma3, cudaFuncAttributeMaxDynamicSharedMemorySize, SMEM_GEMM);
        cudaFuncSetAttribute(k_xw_mma3, cudaFuncAttributeMaxDynamicSharedMemorySize, SMEM_GEMM);
        smem_set = 1;
    }

    // CSR build
    k_zero_cnt<<<SCAN_BLKS, 256>>>();
    k_count<<<NE / 256, 256>>>(edst);
    k_scan1<<<SCAN_BLKS, 256>>>();
    k_scan2<<<1, 256>>>();
    k_scan3<<<SCAN_BLKS, 256>>>();
    k_scatter<<<NE / 256, 256>>>(esrc, edst, etyp);

    // weight prep (tf32 pre-rounded, K-major)
    k_wtrans<<<(NV * DD * KPAD) / 256, 256>>>(wp0, wp1, wp2);
    k_wprep<<<(NW * DD + 255) / 256, 256>>>(basis, comp);
    k_wqk<<<(RR * DD + 255) / 256, 256>>>(attq, attk);

    // projections: grid (157 m-tiles, 3 views)
    dim3 gp((NS + 127) / 128, NV);
    k_proj_mma3<<<gp, 256, SMEM_GEMM>>>(x0, x1, x2, bp0, bp1, bp2);

    // xwt = h @ w6 : grid (469 m-tiles, 6 n-tiles)
    dim3 gx((NTT + 127) / 128, RR);
    k_xw_mma3<<<gx, 256, SMEM_GEMM>>>();

    // attention scalars per (relation, node)
    k_qk<<<NTT / 8, 256>>>();

    // softmax + aggregation + relu
    k_aggregate<<<NTT / 8, 256>>>(cbias);

    // final classification head
    k_final<<<NS / 8, 256>>>(wint, bint, out);
}